// round 2
// baseline (speedup 1.0000x reference)
#include <cuda_runtime.h>
#include <cuda_fp16.h>

#define T_TAB 8192
#define D_MAX 36.0f
#define NGAUSS 300

__device__ __align__(16) __half g_table[T_TAB * 128];   // W(d) lookup, fp16
__device__ __align__(16) __half g_W[67108864];          // [b][i][j][h] fp16, 134 MB
__device__ __align__(16) float  g_x[32 * 128 * 128];
__device__ __align__(16) float  g_f[32 * 128 * 128];

__device__ __forceinline__ float sspf(float x) {
    return fmaxf(x, 0.0f) + log1pf(__expf(-fabsf(x))) - 0.69314718055994531f;
}

// ---- build W(d) table: 256 blocks x 128 threads, 32 rows each ----
__global__ void k_table(const float* __restrict__ w1, const float* __restrict__ b1,
                        const float* __restrict__ w2, const float* __restrict__ b2)
{
    __shared__ float w1s[40 * 128];
    __shared__ float rbf_s[32 * 40];
    __shared__ float As[32 * 128];
    const float hstep = D_MAX / (float)T_TAB;
    const float dc = 30.0f / 299.0f;
    const int t0 = blockIdx.x * 32, h = threadIdx.x;

    float dmin = (float)t0 * hstep, dmax = (float)(t0 + 31) * hstep;
    int glo = (int)floorf((dmin - 1.4f) / dc); if (glo < 0) glo = 0;
    int ghi = (int)ceilf((dmax + 1.4f) / dc);  if (ghi > NGAUSS - 1) ghi = NGAUSS - 1;
    int ng = ghi - glo + 1; if (ng < 0) ng = 0; if (ng > 40) ng = 40;

    for (int idx = h; idx < ng * 128; idx += 128) w1s[idx] = w1[glo * 128 + idx];
    for (int idx = h; idx < 32 * ng; idx += 128) {
        int t = idx / ng, g = idx % ng;
        float d = (float)(t0 + t) * hstep;
        float u = d - (float)(glo + g) * dc;
        rbf_s[t * 40 + g] = __expf(-10.0f * u * u);
    }
    __syncthreads();

    float acc[32];
#pragma unroll
    for (int t = 0; t < 32; t++) acc[t] = 0.0f;
    for (int g = 0; g < ng; g++) {
        float w = w1s[g * 128 + h];
#pragma unroll
        for (int t = 0; t < 32; t++) acc[t] += rbf_s[t * 40 + g] * w;
    }
    float bb = b1[h];
#pragma unroll
    for (int t = 0; t < 32; t++) As[t * 128 + h] = sspf(acc[t] + bb);
    __syncthreads();

#pragma unroll
    for (int t = 0; t < 32; t++) acc[t] = 0.0f;
    for (int k = 0; k < 128; k++) {
        float w = __ldg(&w2[k * 128 + h]);   // 64 KB, L2-hot across blocks
#pragma unroll
        for (int t = 0; t < 32; t++) acc[t] += As[t * 128 + k] * w;
    }
    float b2v = b2[h];
#pragma unroll
    for (int t = 0; t < 32; t++)
        g_table[(t0 + t) * 128 + h] = __float2half(acc[t] + b2v);
}

// ---- x = emb[z] ----
__global__ void k_init(const int* __restrict__ z, const float* __restrict__ emb)
{
    int idx = blockIdx.x * 256 + threadIdx.x;
    if (idx < 4096 * 32) {
        int row = idx >> 5, h4 = idx & 31;
        int zi = z[row];
        float4 v = *reinterpret_cast<const float4*>(emb + zi * 128 + h4 * 4);
        *reinterpret_cast<float4*>(g_x + row * 128 + h4 * 4) = v;
    }
}

// ---- materialize W via table interp, symmetric. grid (128 i, 32 b) x 256 ----
__global__ void k_W(const float* __restrict__ r)
{
    __shared__ float rx[128], ry[128], rz[128], frac_s[128];
    __shared__ int idx_s[128];
    const int b = blockIdx.y, i = blockIdx.x, tid = threadIdx.x;
    const float inv_h = (float)T_TAB / D_MAX;

    if (tid < 128) {
        const float* rp = r + (b * 128 + tid) * 3;
        rx[tid] = rp[0]; ry[tid] = rp[1]; rz[tid] = rp[2];
    }
    __syncthreads();
    if (tid < 128) {
        float dx = rx[i] - rx[tid], dy = ry[i] - ry[tid], dz = rz[i] - rz[tid];
        float d = sqrtf(dx * dx + dy * dy + dz * dz + 1e-12f);
        float t = fminf(d * inv_h, (float)(T_TAB - 1) - 1e-3f);
        int i0 = (int)t;
        idx_s[tid] = i0; frac_s[tid] = t - (float)i0;
    }
    __syncthreads();

    int ntask = (128 - i) * 32;      // j = i..127 (symmetry), 32 half4-groups
    for (int task = tid; task < ntask; task += 256) {
        int j = i + (task >> 5), h4 = task & 31;
        int i0 = idx_s[j];
        float fr = frac_s[j];
        const __half* tp = g_table + i0 * 128 + h4 * 4;
        uint2 ua = *reinterpret_cast<const uint2*>(tp);
        uint2 ub = *reinterpret_cast<const uint2*>(tp + 128);
        __half2 a01 = *reinterpret_cast<__half2*>(&ua.x);
        __half2 a23 = *reinterpret_cast<__half2*>(&ua.y);
        __half2 b01 = *reinterpret_cast<__half2*>(&ub.x);
        __half2 b23 = *reinterpret_cast<__half2*>(&ub.y);
        float2 fa0 = __half22float2(a01), fa1 = __half22float2(a23);
        float2 fb0 = __half22float2(b01), fb1 = __half22float2(b23);
        __half2 h01 = __floats2half2_rn(fa0.x + fr * (fb0.x - fa0.x),
                                        fa0.y + fr * (fb0.y - fa0.y));
        __half2 h23 = __floats2half2_rn(fa1.x + fr * (fb1.x - fa1.x),
                                        fa1.y + fr * (fb1.y - fa1.y));
        uint2 ov;
        ov.x = *reinterpret_cast<unsigned*>(&h01);
        ov.y = *reinterpret_cast<unsigned*>(&h23);
        *reinterpret_cast<uint2*>(g_W + ((b * 128 + i) * 128 + j) * 128 + h4 * 4) = ov;
        *reinterpret_cast<uint2*>(g_W + ((b * 128 + j) * 128 + i) * 128 + h4 * 4) = ov;
    }
}

// ---- f = x @ w_in2f. 128 blocks x 256 threads, 32 rows each ----
__global__ void k_f(const float* __restrict__ w)
{
    extern __shared__ float sm[];
    float* w_s = sm;            // [128][128]
    float* x_s = sm + 16384;    // [32][128]
    const int r0 = blockIdx.x * 32, tid = threadIdx.x;
    for (int idx = tid; idx < 16384; idx += 256) w_s[idx] = w[idx];
    const float* xp = g_x + r0 * 128;
    for (int idx = tid; idx < 4096; idx += 256) x_s[idx] = xp[idx];
    __syncthreads();
    const int ig = tid >> 5, hg = tid & 31;
    float a4[4][4];
#pragma unroll
    for (int rr = 0; rr < 4; rr++)
#pragma unroll
        for (int c = 0; c < 4; c++) a4[rr][c] = 0.0f;
    for (int k = 0; k < 128; k++) {
        float4 wb = *reinterpret_cast<const float4*>(w_s + k * 128 + hg * 4);
#pragma unroll
        for (int rr = 0; rr < 4; rr++) {
            float yv = x_s[(ig * 4 + rr) * 128 + k];
            a4[rr][0] += yv * wb.x; a4[rr][1] += yv * wb.y;
            a4[rr][2] += yv * wb.z; a4[rr][3] += yv * wb.w;
        }
    }
#pragma unroll
    for (int rr = 0; rr < 4; rr++)
        *reinterpret_cast<float4*>(g_f + (r0 + ig * 4 + rr) * 128 + hg * 4) =
            make_float4(a4[rr][0], a4[rr][1], a4[rr][2], a4[rr][3]);
}

// ---- cfconv + fused epilogue + residual. grid (4 itile, 32 b) x 256 ----
__global__ void k_cf(const float* __restrict__ w_f2out, const float* __restrict__ b_f2out,
                     const float* __restrict__ w_out, const float* __restrict__ b_out)
{
    extern __shared__ float sm[];
    float* buf0 = sm;             // [16384] f_s, then wbuf
    float* y_s  = buf0 + 16384;   // [32][128]
    float* y2_s = y_s + 4096;     // [32][128]
    float* red  = y2_s + 4096;    // [8][8][128]
    const int b = blockIdx.y, it = blockIdx.x, tid = threadIdx.x;

    const float* fb = g_f + b * 16384;
    for (int idx = tid; idx < 4096; idx += 256)
        *reinterpret_cast<float4*>(buf0 + idx * 4) =
            *reinterpret_cast<const float4*>(fb + idx * 4);
    __syncthreads();

    const int jg = tid >> 5, h4 = tid & 31;
    for (int io = 0; io < 4; io++) {
        float acc[8][4];
#pragma unroll
        for (int ii = 0; ii < 8; ii++)
#pragma unroll
            for (int c = 0; c < 4; c++) acc[ii][c] = 0.0f;
        const int ibase = it * 32 + io * 8;
        const __half* Wp = g_W + (b * 128 + ibase) * 16384;
        for (int jj = 0; jj < 16; jj++) {
            int j = jg * 16 + jj;
            float4 f4 = *reinterpret_cast<const float4*>(buf0 + j * 128 + h4 * 4);
            const __half* wp = Wp + j * 128 + h4 * 4;
#pragma unroll
            for (int ii = 0; ii < 8; ii++) {
                uint2 u = *reinterpret_cast<const uint2*>(wp + ii * 16384);
                __half2 w01 = *reinterpret_cast<__half2*>(&u.x);
                __half2 w23 = *reinterpret_cast<__half2*>(&u.y);
                float2 p0 = __half22float2(w01), p1 = __half22float2(w23);
                acc[ii][0] += p0.x * f4.x; acc[ii][1] += p0.y * f4.y;
                acc[ii][2] += p1.x * f4.z; acc[ii][3] += p1.y * f4.w;
            }
        }
#pragma unroll
        for (int ii = 0; ii < 8; ii++)
            *reinterpret_cast<float4*>(red + (jg * 8 + ii) * 128 + h4 * 4) =
                make_float4(acc[ii][0], acc[ii][1], acc[ii][2], acc[ii][3]);
        __syncthreads();
#pragma unroll
        for (int rr = 0; rr < 4; rr++) {
            int idx = tid + rr * 256;          // (ii, h)
            int ii = idx >> 7, h = idx & 127;
            float s = 0.0f;
#pragma unroll
            for (int g2 = 0; g2 < 8; g2++) s += red[(g2 * 8 + ii) * 128 + h];
            y_s[(io * 8 + ii) * 128 + h] = s;
        }
        __syncthreads();
    }

    // epilogue: y2 = ssp(y@w_f2out+b); v = y2@w_out+b; x += v
    for (int idx = tid; idx < 16384; idx += 256) buf0[idx] = w_f2out[idx];
    __syncthreads();
    const int ig = tid >> 5, hg = tid & 31;
    float a4[4][4];
#pragma unroll
    for (int rr = 0; rr < 4; rr++)
#pragma unroll
        for (int c = 0; c < 4; c++) a4[rr][c] = 0.0f;
    for (int k = 0; k < 128; k++) {
        float4 wb = *reinterpret_cast<const float4*>(buf0 + k * 128 + hg * 4);
#pragma unroll
        for (int rr = 0; rr < 4; rr++) {
            float yv = y_s[(ig * 4 + rr) * 128 + k];
            a4[rr][0] += yv * wb.x; a4[rr][1] += yv * wb.y;
            a4[rr][2] += yv * wb.z; a4[rr][3] += yv * wb.w;
        }
    }
    {
        float4 bb = *reinterpret_cast<const float4*>(b_f2out + hg * 4);
#pragma unroll
        for (int rr = 0; rr < 4; rr++)
            *reinterpret_cast<float4*>(y2_s + (ig * 4 + rr) * 128 + hg * 4) =
                make_float4(sspf(a4[rr][0] + bb.x), sspf(a4[rr][1] + bb.y),
                            sspf(a4[rr][2] + bb.z), sspf(a4[rr][3] + bb.w));
    }
    __syncthreads();
    for (int idx = tid; idx < 16384; idx += 256) buf0[idx] = w_out[idx];
    __syncthreads();
#pragma unroll
    for (int rr = 0; rr < 4; rr++)
#pragma unroll
        for (int c = 0; c < 4; c++) a4[rr][c] = 0.0f;
    for (int k = 0; k < 128; k++) {
        float4 wb = *reinterpret_cast<const float4*>(buf0 + k * 128 + hg * 4);
#pragma unroll
        for (int rr = 0; rr < 4; rr++) {
            float yv = y2_s[(ig * 4 + rr) * 128 + k];
            a4[rr][0] += yv * wb.x; a4[rr][1] += yv * wb.y;
            a4[rr][2] += yv * wb.z; a4[rr][3] += yv * wb.w;
        }
    }
    {
        float4 bb = *reinterpret_cast<const float4*>(b_out + hg * 4);
#pragma unroll
        for (int rr = 0; rr < 4; rr++) {
            float* xp = g_x + (b * 128 + it * 32 + ig * 4 + rr) * 128 + hg * 4;
            float4 xv = *reinterpret_cast<float4*>(xp);
            xv.x += a4[rr][0] + bb.x; xv.y += a4[rr][1] + bb.y;
            xv.z += a4[rr][2] + bb.z; xv.w += a4[rr][3] + bb.w;
            *reinterpret_cast<float4*>(xp) = xv;
        }
    }
}

// ---- readout: out = ssp(x@w_aw1+b)@w_aw2 + b. 128 blocks x 256 ----
__global__ void k_ro(const float* __restrict__ w1, const float* __restrict__ b1,
                     const float* __restrict__ w2, const float* __restrict__ b2,
                     float* __restrict__ out)
{
    extern __shared__ float sm[];
    float* w_s = sm;            // [128][128]
    float* x_s = w_s + 16384;   // [32][128]
    float* y_s = x_s + 4096;    // [32][128]
    float* w2s = y_s + 4096;    // [128]
    float* part = w2s + 128;    // [256]
    const int r0 = blockIdx.x * 32, tid = threadIdx.x;
    for (int idx = tid; idx < 16384; idx += 256) w_s[idx] = w1[idx];
    const float* xp = g_x + r0 * 128;
    for (int idx = tid; idx < 4096; idx += 256) x_s[idx] = xp[idx];
    if (tid < 128) w2s[tid] = w2[tid];
    __syncthreads();
    const int ig = tid >> 5, hg = tid & 31;
    float a4[4][4];
#pragma unroll
    for (int rr = 0; rr < 4; rr++)
#pragma unroll
        for (int c = 0; c < 4; c++) a4[rr][c] = 0.0f;
    for (int k = 0; k < 128; k++) {
        float4 wb = *reinterpret_cast<const float4*>(w_s + k * 128 + hg * 4);
#pragma unroll
        for (int rr = 0; rr < 4; rr++) {
            float yv = x_s[(ig * 4 + rr) * 128 + k];
            a4[rr][0] += yv * wb.x; a4[rr][1] += yv * wb.y;
            a4[rr][2] += yv * wb.z; a4[rr][3] += yv * wb.w;
        }
    }
    {
        float4 bb = *reinterpret_cast<const float4*>(b1 + hg * 4);
#pragma unroll
        for (int rr = 0; rr < 4; rr++)
            *reinterpret_cast<float4*>(y_s + (ig * 4 + rr) * 128 + hg * 4) =
                make_float4(sspf(a4[rr][0] + bb.x), sspf(a4[rr][1] + bb.y),
                            sspf(a4[rr][2] + bb.z), sspf(a4[rr][3] + bb.w));
    }
    __syncthreads();
    {
        int row = tid >> 3, seg = tid & 7;
        float s = 0.0f;
#pragma unroll
        for (int t = 0; t < 16; t++)
            s += y_s[row * 128 + seg * 16 + t] * w2s[seg * 16 + t];
        part[tid] = s;
    }
    __syncthreads();
    if (tid < 32) {
        float s2 = 0.0f;
#pragma unroll
        for (int q = 0; q < 8; q++) s2 += part[tid * 8 + q];
        out[r0 + tid] = s2 + b2[0];
    }
}

extern "C" void kernel_launch(void* const* d_in, const int* in_sizes, int n_in,
                              void* d_out, int out_size)
{
    const int*   z       = (const int*)  d_in[0];
    const float* r       = (const float*)d_in[1];
    const float* emb     = (const float*)d_in[2];
    const float* w_in2f  = (const float*)d_in[3];
    const float* w_f1    = (const float*)d_in[4];
    const float* b_f1    = (const float*)d_in[5];
    const float* w_f2    = (const float*)d_in[6];
    const float* b_f2    = (const float*)d_in[7];
    const float* w_f2out = (const float*)d_in[8];
    const float* b_f2out = (const float*)d_in[9];
    const float* w_out   = (const float*)d_in[10];
    const float* b_out   = (const float*)d_in[11];
    const float* w_aw1   = (const float*)d_in[12];
    const float* b_aw1   = (const float*)d_in[13];
    const float* w_aw2   = (const float*)d_in[14];
    const float* b_aw2   = (const float*)d_in[15];
    float* out = (float*)d_out;

    cudaFuncSetAttribute(k_f,  cudaFuncAttributeMaxDynamicSharedMemorySize, 96 * 1024);
    cudaFuncSetAttribute(k_cf, cudaFuncAttributeMaxDynamicSharedMemorySize, 144 * 1024);
    cudaFuncSetAttribute(k_ro, cudaFuncAttributeMaxDynamicSharedMemorySize, 112 * 1024);

    k_table<<<256, 128>>>(w_f1, b_f1, w_f2, b_f2);
    k_init<<<512, 256>>>(z, emb);
    k_W<<<dim3(128, 32), 256>>>(r);
    for (int it = 0; it < 3; it++) {
        k_f <<<128, 256, 81920>>>(w_in2f);
        k_cf<<<dim3(4, 32), 256, 131072>>>(w_f2out, b_f2out, w_out, b_out);
    }
    k_ro<<<128, 256, 99856>>>(w_aw1, b_aw1, w_aw2, b_aw2, out);
}

// round 3
// speedup vs baseline: 1.9985x; 1.9985x over previous
#include <cuda_runtime.h>
#include <cuda_fp16.h>

#define T_TAB 8192
#define D_MAX 36.0f
#define NGAUSS 300

__device__ __align__(16) float g_tabf[T_TAB * 128];    // fp32 W(d) table (4 MB)
__device__ __align__(16) uint4 g_tab2u[T_TAB * 32];    // packed (W_t,W_t+1) half2 (4 MB)
__device__ __align__(16) float g_x[4096 * 128];        // x0 (never updated)
__device__ __align__(16) float g_fA[4096 * 128];
__device__ __align__(16) float g_fB[4096 * 128];
__device__ __align__(16) float g_ysum[4096 * 128];     // sum of y2 over iterations
__device__ __align__(16) float g_combo[128 * 128];     // w_out @ w_in2f
__device__ __align__(16) float g_fbias[128];           // b_out @ w_in2f

__device__ __forceinline__ float sspf(float x) {
    return fmaxf(x, 0.0f) + log1pf(__expf(-fabsf(x))) - 0.69314718055994531f;
}

// ---- fp32 W(d) table: 256 blocks x 128 threads, 32 rows each ----
__global__ void k_table(const float* __restrict__ w1, const float* __restrict__ b1,
                        const float* __restrict__ w2, const float* __restrict__ b2)
{
    __shared__ float w1s[40 * 128];
    __shared__ float rbf_s[32 * 40];
    __shared__ float As[32 * 128];
    const float hstep = D_MAX / (float)T_TAB;
    const float dc = 30.0f / 299.0f;
    const int t0 = blockIdx.x * 32, h = threadIdx.x;

    float dmin = (float)t0 * hstep, dmax = (float)(t0 + 31) * hstep;
    int glo = (int)floorf((dmin - 1.4f) / dc); if (glo < 0) glo = 0;
    int ghi = (int)ceilf((dmax + 1.4f) / dc);  if (ghi > NGAUSS - 1) ghi = NGAUSS - 1;
    int ng = ghi - glo + 1; if (ng < 0) ng = 0; if (ng > 40) ng = 40;

    for (int idx = h; idx < ng * 128; idx += 128) w1s[idx] = w1[glo * 128 + idx];
    for (int idx = h; idx < 32 * ng; idx += 128) {
        int t = idx / ng, g = idx % ng;
        float d = (float)(t0 + t) * hstep;
        float u = d - (float)(glo + g) * dc;
        rbf_s[t * 40 + g] = __expf(-10.0f * u * u);
    }
    __syncthreads();

    float acc[32];
#pragma unroll
    for (int t = 0; t < 32; t++) acc[t] = 0.0f;
    for (int g = 0; g < ng; g++) {
        float w = w1s[g * 128 + h];
#pragma unroll
        for (int t = 0; t < 32; t++) acc[t] += rbf_s[t * 40 + g] * w;
    }
    float bb = b1[h];
#pragma unroll
    for (int t = 0; t < 32; t++) As[t * 128 + h] = sspf(acc[t] + bb);
    __syncthreads();

#pragma unroll
    for (int t = 0; t < 32; t++) acc[t] = 0.0f;
    for (int k = 0; k < 128; k++) {
        float w = __ldg(&w2[k * 128 + h]);
#pragma unroll
        for (int t = 0; t < 32; t++) acc[t] += As[t * 128 + k] * w;
    }
    float b2v = b2[h];
#pragma unroll
    for (int t = 0; t < 32; t++)
        g_tabf[(t0 + t) * 128 + h] = acc[t] + b2v;
}

// ---- pack table: entry (t,h4) = {W_t[4h4..+3], W_t+1[4h4..+3]} as 4x half2 ----
__global__ void k_pack()
{
    int g = blockIdx.x * 256 + threadIdx.x;
    if (g >= T_TAB * 32) return;
    int t = g >> 5, h4 = g & 31;
    int tn = min(t + 1, T_TAB - 1);
    const float* a = g_tabf + t * 128 + h4 * 4;
    const float* b = g_tabf + tn * 128 + h4 * 4;
    __half2 a01 = __floats2half2_rn(a[0], a[1]);
    __half2 a23 = __floats2half2_rn(a[2], a[3]);
    __half2 b01 = __floats2half2_rn(b[0], b[1]);
    __half2 b23 = __floats2half2_rn(b[2], b[3]);
    uint4 u;
    u.x = *reinterpret_cast<unsigned*>(&a01);
    u.y = *reinterpret_cast<unsigned*>(&a23);
    u.z = *reinterpret_cast<unsigned*>(&b01);
    u.w = *reinterpret_cast<unsigned*>(&b23);
    g_tab2u[g] = u;
}

// ---- x0 = emb[z], ysum = 0 ----
__global__ void k_init(const int* __restrict__ z, const float* __restrict__ emb)
{
    int idx = blockIdx.x * 256 + threadIdx.x;
    if (idx < 4096 * 32) {
        int row = idx >> 5, h4 = idx & 31;
        int zi = z[row];
        float4 v = *reinterpret_cast<const float4*>(emb + zi * 128 + h4 * 4);
        *reinterpret_cast<float4*>(g_x + row * 128 + h4 * 4) = v;
        *reinterpret_cast<float4*>(g_ysum + row * 128 + h4 * 4) = make_float4(0.f, 0.f, 0.f, 0.f);
    }
}

// ---- w_combo = w_out @ w_in2f ; fbias = b_out @ w_in2f ----
__global__ void k_combo(const float* __restrict__ w_out, const float* __restrict__ b_out,
                        const float* __restrict__ w_in2f)
{
    extern __shared__ float ws[];   // [128][128] w_in2f
    const int tid = threadIdx.x;
    for (int idx = tid; idx < 16384; idx += 256) ws[idx] = w_in2f[idx];
    __syncthreads();
    int rg = tid >> 5, hg = tid & 31;
    int row = blockIdx.x * 8 + rg;
    float a0 = 0, a1 = 0, a2 = 0, a3 = 0;
    for (int m = 0; m < 128; m++) {
        float wo = __ldg(&w_out[row * 128 + m]);
        float4 wb = *reinterpret_cast<const float4*>(ws + m * 128 + hg * 4);
        a0 += wo * wb.x; a1 += wo * wb.y; a2 += wo * wb.z; a3 += wo * wb.w;
    }
    float4 o = make_float4(a0, a1, a2, a3);
    *reinterpret_cast<float4*>(g_combo + row * 128 + hg * 4) = o;
    if (blockIdx.x == 0 && tid < 128) {
        float s = 0.0f;
        for (int m = 0; m < 128; m++) s += __ldg(&b_out[m]) * ws[m * 128 + tid];
        g_fbias[tid] = s;
    }
}

// ---- f0 = x0 @ w_in2f. 256 blocks (16 rows) x 256 threads ----
__global__ void k_f0(const float* __restrict__ w)
{
    extern __shared__ float sm[];
    float* ws = sm;            // 64 KB
    float* xs = sm + 16384;    // 8 KB
    const int r0 = blockIdx.x * 16, tid = threadIdx.x;
    for (int idx = tid; idx < 16384; idx += 256) ws[idx] = w[idx];
    for (int idx = tid; idx < 2048; idx += 256) xs[idx] = g_x[r0 * 128 + idx];
    __syncthreads();
    int rg = tid >> 5, hg = tid & 31;
    float a[2][4];
#pragma unroll
    for (int rr = 0; rr < 2; rr++)
#pragma unroll
        for (int c = 0; c < 4; c++) a[rr][c] = 0.0f;
    for (int k = 0; k < 128; k++) {
        float4 wb = *reinterpret_cast<const float4*>(ws + k * 128 + hg * 4);
        float y0 = xs[(rg * 2) * 128 + k], y1 = xs[(rg * 2 + 1) * 128 + k];
        a[0][0] += y0 * wb.x; a[0][1] += y0 * wb.y; a[0][2] += y0 * wb.z; a[0][3] += y0 * wb.w;
        a[1][0] += y1 * wb.x; a[1][1] += y1 * wb.y; a[1][2] += y1 * wb.z; a[1][3] += y1 * wb.w;
    }
#pragma unroll
    for (int rr = 0; rr < 2; rr++)
        *reinterpret_cast<float4*>(g_fA + (r0 + rg * 2 + rr) * 128 + hg * 4) =
            make_float4(a[rr][0], a[rr][1], a[rr][2], a[rr][3]);
}

// ---- cfconv-from-table + fused epilogue. grid (8 itile, 32 b) x 256 ----
__global__ void __launch_bounds__(256)
k_cf(const float* __restrict__ r, const float* __restrict__ w_f2out,
     const float* __restrict__ b_f2out, int flag)
{
    extern __shared__ char smb[];
    float* buf  = (float*)smb;                    // 64 KB: f_s -> red -> wbuf
    uint2* idf  = (uint2*)(smb + 65536);          // 16 KB: [i_local][j] (idx, fr2)
    float* y_s  = (float*)(smb + 65536 + 16384);  // 8 KB
    float* y2_s = y_s + 2048;                     // 8 KB
    float* rs   = y2_s + 2048;                    // 3*128 floats
    const int it = blockIdx.x, b = blockIdx.y, tid = threadIdx.x;
    const float* f_in  = flag ? g_fB : g_fA;
    float*       f_out = flag ? g_fA : g_fB;
    const float inv_h = (float)T_TAB / D_MAX;

    if (tid < 128) {
        const float* rp = r + (b * 128 + tid) * 3;
        rs[tid] = rp[0]; rs[128 + tid] = rp[1]; rs[256 + tid] = rp[2];
    }
    for (int idx = tid; idx < 4096; idx += 256)
        *reinterpret_cast<float4*>(buf + idx * 4) =
            *reinterpret_cast<const float4*>(f_in + b * 16384 + idx * 4);
    __syncthreads();
    for (int task = tid; task < 2048; task += 256) {
        int il = task >> 7, j = task & 127;
        int ig = it * 16 + il;
        float dx = rs[ig] - rs[j], dy = rs[128 + ig] - rs[128 + j], dz = rs[256 + ig] - rs[256 + j];
        float d = sqrtf(dx * dx + dy * dy + dz * dz + 1e-12f);
        float t = fminf(d * inv_h, 8190.9f);
        int i0 = (int)t;
        __half2 fr2 = __half2half2(__float2half_rn(t - (float)i0));
        idf[task] = make_uint2((unsigned)i0, *reinterpret_cast<unsigned*>(&fr2));
    }
    __syncthreads();

    const int jg = tid >> 5, h4 = tid & 31;
    float acc[16][4];
#pragma unroll
    for (int il = 0; il < 16; il++)
#pragma unroll
        for (int c = 0; c < 4; c++) acc[il][c] = 0.0f;

    for (int jj = 0; jj < 16; jj++) {
        int j = jg * 16 + jj;
        float4 f4 = *reinterpret_cast<const float4*>(buf + j * 128 + h4 * 4);
#pragma unroll
        for (int il = 0; il < 16; il++) {
            uint2 q = idf[il * 128 + j];
            uint4 u = g_tab2u[q.x * 32 + h4];
            __half2 fr2 = *reinterpret_cast<__half2*>(&q.y);
            __half2 a01 = *reinterpret_cast<__half2*>(&u.x);
            __half2 a23 = *reinterpret_cast<__half2*>(&u.y);
            __half2 b01 = *reinterpret_cast<__half2*>(&u.z);
            __half2 b23 = *reinterpret_cast<__half2*>(&u.w);
            __half2 l01 = __hfma2(fr2, __hsub2(b01, a01), a01);
            __half2 l23 = __hfma2(fr2, __hsub2(b23, a23), a23);
            float2 p0 = __half22float2(l01), p1 = __half22float2(l23);
            acc[il][0] = fmaf(p0.x, f4.x, acc[il][0]);
            acc[il][1] = fmaf(p0.y, f4.y, acc[il][1]);
            acc[il][2] = fmaf(p1.x, f4.z, acc[il][2]);
            acc[il][3] = fmaf(p1.y, f4.w, acc[il][3]);
        }
    }
    __syncthreads();   // f_s dead; reuse buf as red[jg][il][h]
#pragma unroll
    for (int il = 0; il < 16; il++)
        *reinterpret_cast<float4*>(buf + (jg * 16 + il) * 128 + h4 * 4) =
            make_float4(acc[il][0], acc[il][1], acc[il][2], acc[il][3]);
    __syncthreads();
#pragma unroll
    for (int k = 0; k < 8; k++) {
        int idx = tid + k * 256;
        int i = idx >> 7, h = idx & 127;
        float s = 0.0f;
#pragma unroll
        for (int g = 0; g < 8; g++) s += buf[(g * 16 + i) * 128 + h];
        y_s[i * 128 + h] = s;
    }
    __syncthreads();   // red dead; reuse buf as weight buffer

    // ---- y2 = ssp(y @ w_f2out + b) ----
    for (int idx = tid; idx < 16384; idx += 256) buf[idx] = w_f2out[idx];
    __syncthreads();
    const int rg = tid >> 5, hg = tid & 31;
    float a[2][4];
#pragma unroll
    for (int rr = 0; rr < 2; rr++)
#pragma unroll
        for (int c = 0; c < 4; c++) a[rr][c] = 0.0f;
    for (int k = 0; k < 128; k++) {
        float4 wb = *reinterpret_cast<const float4*>(buf + k * 128 + hg * 4);
        float y0 = y_s[(rg * 2) * 128 + k], y1 = y_s[(rg * 2 + 1) * 128 + k];
        a[0][0] += y0 * wb.x; a[0][1] += y0 * wb.y; a[0][2] += y0 * wb.z; a[0][3] += y0 * wb.w;
        a[1][0] += y1 * wb.x; a[1][1] += y1 * wb.y; a[1][2] += y1 * wb.z; a[1][3] += y1 * wb.w;
    }
    {
        float4 bb = *reinterpret_cast<const float4*>(b_f2out + hg * 4);
#pragma unroll
        for (int rr = 0; rr < 2; rr++)
            *reinterpret_cast<float4*>(y2_s + (rg * 2 + rr) * 128 + hg * 4) =
                make_float4(sspf(a[rr][0] + bb.x), sspf(a[rr][1] + bb.y),
                            sspf(a[rr][2] + bb.z), sspf(a[rr][3] + bb.w));
    }
    __syncthreads();
    // ---- ysum += y2 ----
#pragma unroll
    for (int k = 0; k < 8; k++) {
        int idx = tid + k * 256;
        int i = idx >> 7, h = idx & 127;
        int grow = (b * 128 + it * 16 + i) * 128 + h;
        g_ysum[grow] += y2_s[i * 128 + h];
    }
    // ---- f_out = f_in + fbias + y2 @ w_combo ----
    for (int idx = tid; idx < 16384; idx += 256) buf[idx] = g_combo[idx];
    __syncthreads();
#pragma unroll
    for (int rr = 0; rr < 2; rr++)
#pragma unroll
        for (int c = 0; c < 4; c++) a[rr][c] = 0.0f;
    for (int k = 0; k < 128; k++) {
        float4 wb = *reinterpret_cast<const float4*>(buf + k * 128 + hg * 4);
        float y0 = y2_s[(rg * 2) * 128 + k], y1 = y2_s[(rg * 2 + 1) * 128 + k];
        a[0][0] += y0 * wb.x; a[0][1] += y0 * wb.y; a[0][2] += y0 * wb.z; a[0][3] += y0 * wb.w;
        a[1][0] += y1 * wb.x; a[1][1] += y1 * wb.y; a[1][2] += y1 * wb.z; a[1][3] += y1 * wb.w;
    }
    {
        float4 fb = *reinterpret_cast<const float4*>(g_fbias + hg * 4);
#pragma unroll
        for (int rr = 0; rr < 2; rr++) {
            int grow = (b * 128 + it * 16 + rg * 2 + rr) * 128 + hg * 4;
            float4 fo = *reinterpret_cast<const float4*>(f_in + grow);
            *reinterpret_cast<float4*>(f_out + grow) =
                make_float4(fo.x + fb.x + a[rr][0], fo.y + fb.y + a[rr][1],
                            fo.z + fb.z + a[rr][2], fo.w + fb.w + a[rr][3]);
        }
    }
}

// ---- readout: x = x0 + ysum@w_out + 3*b_out ; out = ssp(x@w_aw1+b)@w_aw2 + b ----
__global__ void k_ro(const float* __restrict__ w_out, const float* __restrict__ b_out,
                     const float* __restrict__ w1, const float* __restrict__ b1,
                     const float* __restrict__ w2, const float* __restrict__ b2,
                     float* __restrict__ out)
{
    extern __shared__ char smb[];
    float* buf = (float*)smb;                   // 64 KB weights
    float* sy  = (float*)(smb + 65536);         // 8 KB: ysum rows -> yro
    float* xf  = sy + 2048;                     // 8 KB
    float* w2s = xf + 2048;                     // 128
    float* part = w2s + 128;                    // 256
    const int r0 = blockIdx.x * 16, tid = threadIdx.x;

    for (int idx = tid; idx < 16384; idx += 256) buf[idx] = w_out[idx];
    for (int idx = tid; idx < 2048; idx += 256) sy[idx] = g_ysum[r0 * 128 + idx];
    if (tid < 128) w2s[tid] = w2[tid];
    __syncthreads();
    const int rg = tid >> 5, hg = tid & 31;
    float a[2][4];
#pragma unroll
    for (int rr = 0; rr < 2; rr++)
#pragma unroll
        for (int c = 0; c < 4; c++) a[rr][c] = 0.0f;
    for (int k = 0; k < 128; k++) {
        float4 wb = *reinterpret_cast<const float4*>(buf + k * 128 + hg * 4);
        float y0 = sy[(rg * 2) * 128 + k], y1 = sy[(rg * 2 + 1) * 128 + k];
        a[0][0] += y0 * wb.x; a[0][1] += y0 * wb.y; a[0][2] += y0 * wb.z; a[0][3] += y0 * wb.w;
        a[1][0] += y1 * wb.x; a[1][1] += y1 * wb.y; a[1][2] += y1 * wb.z; a[1][3] += y1 * wb.w;
    }
    {
        float4 bb = *reinterpret_cast<const float4*>(b_out + hg * 4);
#pragma unroll
        for (int rr = 0; rr < 2; rr++) {
            int grow = (r0 + rg * 2 + rr) * 128 + hg * 4;
            float4 x0 = *reinterpret_cast<const float4*>(g_x + grow);
            *reinterpret_cast<float4*>(xf + (rg * 2 + rr) * 128 + hg * 4) =
                make_float4(x0.x + a[rr][0] + 3.0f * bb.x, x0.y + a[rr][1] + 3.0f * bb.y,
                            x0.z + a[rr][2] + 3.0f * bb.z, x0.w + a[rr][3] + 3.0f * bb.w);
        }
    }
    __syncthreads();
    for (int idx = tid; idx < 16384; idx += 256) buf[idx] = w1[idx];
    __syncthreads();
#pragma unroll
    for (int rr = 0; rr < 2; rr++)
#pragma unroll
        for (int c = 0; c < 4; c++) a[rr][c] = 0.0f;
    for (int k = 0; k < 128; k++) {
        float4 wb = *reinterpret_cast<const float4*>(buf + k * 128 + hg * 4);
        float y0 = xf[(rg * 2) * 128 + k], y1 = xf[(rg * 2 + 1) * 128 + k];
        a[0][0] += y0 * wb.x; a[0][1] += y0 * wb.y; a[0][2] += y0 * wb.z; a[0][3] += y0 * wb.w;
        a[1][0] += y1 * wb.x; a[1][1] += y1 * wb.y; a[1][2] += y1 * wb.z; a[1][3] += y1 * wb.w;
    }
    __syncthreads();   // sy reads done; reuse as yro
    {
        float4 bb = *reinterpret_cast<const float4*>(b1 + hg * 4);
#pragma unroll
        for (int rr = 0; rr < 2; rr++)
            *reinterpret_cast<float4*>(sy + (rg * 2 + rr) * 128 + hg * 4) =
                make_float4(sspf(a[rr][0] + bb.x), sspf(a[rr][1] + bb.y),
                            sspf(a[rr][2] + bb.z), sspf(a[rr][3] + bb.w));
    }
    __syncthreads();
    {
        int row = tid >> 4, seg = tid & 15;
        float s = 0.0f;
#pragma unroll
        for (int t = 0; t < 8; t++)
            s += sy[row * 128 + seg * 8 + t] * w2s[seg * 8 + t];
        part[tid] = s;
    }
    __syncthreads();
    if (tid < 16) {
        float s = 0.0f;
#pragma unroll
        for (int q = 0; q < 16; q++) s += part[tid * 16 + q];
        out[r0 + tid] = s + b2[0];
    }
}

extern "C" void kernel_launch(void* const* d_in, const int* in_sizes, int n_in,
                              void* d_out, int out_size)
{
    const int*   z       = (const int*)  d_in[0];
    const float* r       = (const float*)d_in[1];
    const float* emb     = (const float*)d_in[2];
    const float* w_in2f  = (const float*)d_in[3];
    const float* w_f1    = (const float*)d_in[4];
    const float* b_f1    = (const float*)d_in[5];
    const float* w_f2    = (const float*)d_in[6];
    const float* b_f2    = (const float*)d_in[7];
    const float* w_f2out = (const float*)d_in[8];
    const float* b_f2out = (const float*)d_in[9];
    const float* w_out   = (const float*)d_in[10];
    const float* b_out   = (const float*)d_in[11];
    const float* w_aw1   = (const float*)d_in[12];
    const float* b_aw1   = (const float*)d_in[13];
    const float* w_aw2   = (const float*)d_in[14];
    const float* b_aw2   = (const float*)d_in[15];
    float* out = (float*)d_out;

    cudaFuncSetAttribute(k_combo, cudaFuncAttributeMaxDynamicSharedMemorySize, 65536);
    cudaFuncSetAttribute(k_f0,    cudaFuncAttributeMaxDynamicSharedMemorySize, 73728);
    cudaFuncSetAttribute(k_cf,    cudaFuncAttributeMaxDynamicSharedMemorySize, 100352);
    cudaFuncSetAttribute(k_ro,    cudaFuncAttributeMaxDynamicSharedMemorySize, 86016);

    k_table<<<256, 128>>>(w_f1, b_f1, w_f2, b_f2);
    k_pack<<<1024, 256>>>();
    k_init<<<512, 256>>>(z, emb);
    k_combo<<<16, 256, 65536>>>(w_out, b_out, w_in2f);
    k_f0<<<256, 256, 73728>>>(w_in2f);
    for (int it = 0; it < 3; it++)
        k_cf<<<dim3(8, 32), 256, 100352>>>(r, w_f2out, b_f2out, it & 1);
    k_ro<<<256, 256, 86016>>>(w_out, b_out, w_aw1, b_aw1, w_aw2, b_aw2, out);
}

// round 4
// speedup vs baseline: 3.1802x; 1.5913x over previous
#include <cuda_runtime.h>
#include <cuda_fp16.h>

#define TC 8192
#define TF 131072
#define D_MAX 36.0f
#define NGAUSS 300

__device__ __align__(16) float g_tabf[TC * 128];        // coarse fp32 W(d) (4 MB)
__device__ __align__(16) uint2 g_tabn[TF * 32];         // fine fp16 nearest table (32 MB)
__device__ __align__(16) float g_x[4096 * 128];
__device__ __align__(16) float g_fA[4096 * 128];
__device__ __align__(16) float g_fB[4096 * 128];
__device__ __align__(16) float g_ysum[4096 * 128];
__device__ __align__(16) float g_combo[128 * 128];
__device__ __align__(16) float g_fbias[128];

__device__ __forceinline__ float sspf(float x) {
    return fmaxf(x, 0.0f) + log1pf(__expf(-fabsf(x))) - 0.69314718055994531f;
}

// ---- coarse fp32 table: 512 blocks x 128 thr, 16 rows each ----
__global__ void k_table(const float* __restrict__ w1, const float* __restrict__ b1,
                        const float* __restrict__ w2, const float* __restrict__ b2)
{
    __shared__ float w1s[32 * 128];
    __shared__ float rbf_s[16 * 32];
    __shared__ float As[16 * 128];
    const float hstep = D_MAX / (float)TC;
    const float dc = 30.0f / 299.0f;
    const int t0 = blockIdx.x * 16, h = threadIdx.x;

    float dmin = (float)t0 * hstep, dmax = (float)(t0 + 15) * hstep;
    int glo = (int)floorf((dmin - 1.4f) / dc); if (glo < 0) glo = 0;
    int ghi = (int)ceilf((dmax + 1.4f) / dc);  if (ghi > NGAUSS - 1) ghi = NGAUSS - 1;
    int ng = ghi - glo + 1; if (ng < 0) ng = 0; if (ng > 32) ng = 32;

    for (int idx = h; idx < ng * 128; idx += 128) w1s[idx] = w1[glo * 128 + idx];
    for (int idx = h; idx < 16 * ng; idx += 128) {
        int t = idx / ng, g = idx % ng;
        float d = (float)(t0 + t) * hstep;
        float u = d - (float)(glo + g) * dc;
        rbf_s[t * 32 + g] = __expf(-10.0f * u * u);
    }
    __syncthreads();

    float acc[16];
#pragma unroll
    for (int t = 0; t < 16; t++) acc[t] = 0.0f;
    for (int g = 0; g < ng; g++) {
        float w = w1s[g * 128 + h];
#pragma unroll
        for (int t = 0; t < 16; t++) acc[t] += rbf_s[t * 32 + g] * w;
    }
    float bb = b1[h];
#pragma unroll
    for (int t = 0; t < 16; t++) As[t * 128 + h] = sspf(acc[t] + bb);
    __syncthreads();

#pragma unroll
    for (int t = 0; t < 16; t++) acc[t] = 0.0f;
    for (int k = 0; k < 128; k++) {
        float w = __ldg(&w2[k * 128 + h]);
#pragma unroll
        for (int t = 0; t < 16; t++) acc[t] += As[t * 128 + k] * w;
    }
    float b2v = b2[h];
#pragma unroll
    for (int t = 0; t < 16; t++)
        g_tabf[(t0 + t) * 128 + h] = acc[t] + b2v;
}

// ---- fine table: entry (t,h4) = W(t*36/TF)[4h4..+3] as 2x half2 ----
__global__ void k_pack()
{
    int g = blockIdx.x * 256 + threadIdx.x;       // over TF*32
    int t = g >> 5, h4 = g & 31;
    int u = t >> 4;
    float fr = (float)(t & 15) * 0.0625f;
    int un = min(u + 1, TC - 1);
    float4 a = *reinterpret_cast<const float4*>(g_tabf + u * 128 + h4 * 4);
    float4 b = *reinterpret_cast<const float4*>(g_tabf + un * 128 + h4 * 4);
    __half2 h01 = __floats2half2_rn(a.x + fr * (b.x - a.x), a.y + fr * (b.y - a.y));
    __half2 h23 = __floats2half2_rn(a.z + fr * (b.z - a.z), a.w + fr * (b.w - a.w));
    uint2 o;
    o.x = *reinterpret_cast<unsigned*>(&h01);
    o.y = *reinterpret_cast<unsigned*>(&h23);
    g_tabn[g] = o;
}

// ---- fused setup: blocks 0-255 = gather+f0(+zero ysum), 256-263 = combo, 264 = fbias ----
__global__ void k_setup(const int* __restrict__ z, const float* __restrict__ emb,
                        const float* __restrict__ w_in2f, const float* __restrict__ w_out,
                        const float* __restrict__ b_out)
{
    extern __shared__ float sm[];
    float* ws = sm;            // [128][128]
    float* xs = sm + 16384;    // [16][128]
    const int bx = blockIdx.x, tid = threadIdx.x;

    for (int idx = tid; idx < 16384; idx += 256) ws[idx] = w_in2f[idx];
    if (bx < 256) {
        int r0 = bx * 16;
        for (int idx = tid; idx < 2048; idx += 256) {
            int i = idx >> 7, h = idx & 127;
            int zi = z[r0 + i];
            float v = emb[zi * 128 + h];
            xs[idx] = v;
            g_x[r0 * 128 + idx] = v;
            g_ysum[r0 * 128 + idx] = 0.0f;
        }
    } else if (bx < 264) {
        int r0 = (bx - 256) * 16;
        for (int idx = tid; idx < 2048; idx += 256) xs[idx] = w_out[r0 * 128 + idx];
    }
    __syncthreads();

    if (bx == 264) {
        if (tid < 128) {
            float s = 0.0f;
            for (int m = 0; m < 128; m++) s += __ldg(&b_out[m]) * ws[m * 128 + tid];
            g_fbias[tid] = s;
        }
        return;
    }
    const int rg = tid >> 5, hg = tid & 31;
    float a[2][4];
#pragma unroll
    for (int rr = 0; rr < 2; rr++)
#pragma unroll
        for (int c = 0; c < 4; c++) a[rr][c] = 0.0f;
    for (int k = 0; k < 128; k++) {
        float4 wb = *reinterpret_cast<const float4*>(ws + k * 128 + hg * 4);
        float y0 = xs[(rg * 2) * 128 + k], y1 = xs[(rg * 2 + 1) * 128 + k];
        a[0][0] += y0 * wb.x; a[0][1] += y0 * wb.y; a[0][2] += y0 * wb.z; a[0][3] += y0 * wb.w;
        a[1][0] += y1 * wb.x; a[1][1] += y1 * wb.y; a[1][2] += y1 * wb.z; a[1][3] += y1 * wb.w;
    }
    float* outp = (bx < 256) ? (g_fA + bx * 16 * 128) : (g_combo + (bx - 256) * 16 * 128);
#pragma unroll
    for (int rr = 0; rr < 2; rr++)
        *reinterpret_cast<float4*>(outp + (rg * 2 + rr) * 128 + hg * 4) =
            make_float4(a[rr][0], a[rr][1], a[rr][2], a[rr][3]);
}

// ---- cfconv (nearest fine table) + fused epilogue. grid (8 itile, 32 b) x 256 ----
__global__ void __launch_bounds__(256)
k_cf(const float* __restrict__ r, const float* __restrict__ w_f2out,
     const float* __restrict__ b_f2out, int flag)
{
    extern __shared__ char smb[];
    float*    buf   = (float*)smb;                    // 64 KB: f_s -> red -> wbuf
    unsigned* idx_s = (unsigned*)(smb + 65536);       // 8 KB: [j][16 il]
    float*    y_s   = (float*)(smb + 73728);          // 8 KB
    float*    y2_s  = (float*)(smb + 81920);          // 8 KB
    float*    rs    = (float*)(smb + 90112);          // 1.5 KB
    const int it = blockIdx.x, b = blockIdx.y, tid = threadIdx.x;
    const float* f_in  = flag ? g_fB : g_fA;
    float*       f_out = flag ? g_fA : g_fB;
    const float inv_h = (float)TF / D_MAX;

    if (tid < 128) {
        const float* rp = r + (b * 128 + tid) * 3;
        rs[tid] = rp[0]; rs[128 + tid] = rp[1]; rs[256 + tid] = rp[2];
    }
    for (int idx = tid; idx < 4096; idx += 256)
        *reinterpret_cast<float4*>(buf + idx * 4) =
            *reinterpret_cast<const float4*>(f_in + b * 16384 + idx * 4);
    __syncthreads();
    for (int task = tid; task < 2048; task += 256) {
        int j = task >> 4, il = task & 15;
        int ig = it * 16 + il;
        float dx = rs[ig] - rs[j], dy = rs[128 + ig] - rs[128 + j], dz = rs[256 + ig] - rs[256 + j];
        float d = sqrtf(dx * dx + dy * dy + dz * dz + 1e-12f);
        float t = fminf(d * inv_h + 0.5f, (float)(TF - 1));
        idx_s[task] = (unsigned)t;
    }
    __syncthreads();

    const int jg = tid >> 5, h4 = tid & 31;
    float acc[16][4];
#pragma unroll
    for (int il = 0; il < 16; il++)
#pragma unroll
        for (int c = 0; c < 4; c++) acc[il][c] = 0.0f;

    for (int jj = 0; jj < 16; jj++) {
        int j = jg * 16 + jj;
        float4 f4 = *reinterpret_cast<const float4*>(buf + j * 128 + h4 * 4);
        const unsigned* ip = idx_s + j * 16;
        uint4 q0 = *reinterpret_cast<const uint4*>(ip);
        uint4 q1 = *reinterpret_cast<const uint4*>(ip + 4);
        uint4 q2 = *reinterpret_cast<const uint4*>(ip + 8);
        uint4 q3 = *reinterpret_cast<const uint4*>(ip + 12);
        unsigned tv[16] = {q0.x, q0.y, q0.z, q0.w, q1.x, q1.y, q1.z, q1.w,
                           q2.x, q2.y, q2.z, q2.w, q3.x, q3.y, q3.z, q3.w};
#pragma unroll
        for (int il = 0; il < 16; il++) {
            uint2 u = g_tabn[tv[il] * 32 + h4];
            __half2 w01 = *reinterpret_cast<__half2*>(&u.x);
            __half2 w23 = *reinterpret_cast<__half2*>(&u.y);
            float2 p0 = __half22float2(w01), p1 = __half22float2(w23);
            acc[il][0] = fmaf(p0.x, f4.x, acc[il][0]);
            acc[il][1] = fmaf(p0.y, f4.y, acc[il][1]);
            acc[il][2] = fmaf(p1.x, f4.z, acc[il][2]);
            acc[il][3] = fmaf(p1.y, f4.w, acc[il][3]);
        }
    }
    __syncthreads();   // f_s dead; reuse buf as red[jg][il][h]
#pragma unroll
    for (int il = 0; il < 16; il++)
        *reinterpret_cast<float4*>(buf + (jg * 16 + il) * 128 + h4 * 4) =
            make_float4(acc[il][0], acc[il][1], acc[il][2], acc[il][3]);
    __syncthreads();
#pragma unroll
    for (int k = 0; k < 8; k++) {
        int idx = tid + k * 256;
        int i = idx >> 7, h = idx & 127;
        float s = 0.0f;
#pragma unroll
        for (int g = 0; g < 8; g++) s += buf[(g * 16 + i) * 128 + h];
        y_s[i * 128 + h] = s;
    }
    __syncthreads();   // red dead; reuse buf for weights

    // ---- y2 = ssp(y @ w_f2out + b) ----
    for (int idx = tid; idx < 16384; idx += 256) buf[idx] = w_f2out[idx];
    __syncthreads();
    const int rg = tid >> 5, hg = tid & 31;
    float a[2][4];
#pragma unroll
    for (int rr = 0; rr < 2; rr++)
#pragma unroll
        for (int c = 0; c < 4; c++) a[rr][c] = 0.0f;
    for (int k = 0; k < 128; k++) {
        float4 wb = *reinterpret_cast<const float4*>(buf + k * 128 + hg * 4);
        float y0 = y_s[(rg * 2) * 128 + k], y1 = y_s[(rg * 2 + 1) * 128 + k];
        a[0][0] += y0 * wb.x; a[0][1] += y0 * wb.y; a[0][2] += y0 * wb.z; a[0][3] += y0 * wb.w;
        a[1][0] += y1 * wb.x; a[1][1] += y1 * wb.y; a[1][2] += y1 * wb.z; a[1][3] += y1 * wb.w;
    }
    {
        float4 bb = *reinterpret_cast<const float4*>(b_f2out + hg * 4);
#pragma unroll
        for (int rr = 0; rr < 2; rr++)
            *reinterpret_cast<float4*>(y2_s + (rg * 2 + rr) * 128 + hg * 4) =
                make_float4(sspf(a[rr][0] + bb.x), sspf(a[rr][1] + bb.y),
                            sspf(a[rr][2] + bb.z), sspf(a[rr][3] + bb.w));
    }
    __syncthreads();
    // ---- ysum += y2 ----
#pragma unroll
    for (int k = 0; k < 8; k++) {
        int idx = tid + k * 256;
        int i = idx >> 7, h = idx & 127;
        int grow = (b * 128 + it * 16 + i) * 128 + h;
        g_ysum[grow] += y2_s[i * 128 + h];
    }
    // ---- f_out = f_in + fbias + y2 @ w_combo ----
    for (int idx = tid; idx < 16384; idx += 256) buf[idx] = g_combo[idx];
    __syncthreads();
#pragma unroll
    for (int rr = 0; rr < 2; rr++)
#pragma unroll
        for (int c = 0; c < 4; c++) a[rr][c] = 0.0f;
    for (int k = 0; k < 128; k++) {
        float4 wb = *reinterpret_cast<const float4*>(buf + k * 128 + hg * 4);
        float y0 = y2_s[(rg * 2) * 128 + k], y1 = y2_s[(rg * 2 + 1) * 128 + k];
        a[0][0] += y0 * wb.x; a[0][1] += y0 * wb.y; a[0][2] += y0 * wb.z; a[0][3] += y0 * wb.w;
        a[1][0] += y1 * wb.x; a[1][1] += y1 * wb.y; a[1][2] += y1 * wb.z; a[1][3] += y1 * wb.w;
    }
    {
        float4 fb = *reinterpret_cast<const float4*>(g_fbias + hg * 4);
#pragma unroll
        for (int rr = 0; rr < 2; rr++) {
            int grow = (b * 128 + it * 16 + rg * 2 + rr) * 128 + hg * 4;
            float4 fo = *reinterpret_cast<const float4*>(f_in + grow);
            *reinterpret_cast<float4*>(f_out + grow) =
                make_float4(fo.x + fb.x + a[rr][0], fo.y + fb.y + a[rr][1],
                            fo.z + fb.z + a[rr][2], fo.w + fb.w + a[rr][3]);
        }
    }
}

// ---- readout ----
__global__ void k_ro(const float* __restrict__ w_out, const float* __restrict__ b_out,
                     const float* __restrict__ w1, const float* __restrict__ b1,
                     const float* __restrict__ w2, const float* __restrict__ b2,
                     float* __restrict__ out)
{
    extern __shared__ char smb[];
    float* buf = (float*)smb;                   // 64 KB weights
    float* sy  = (float*)(smb + 65536);         // 8 KB: ysum rows -> yro
    float* xf  = sy + 2048;                     // 8 KB
    float* w2s = xf + 2048;                     // 128
    float* part = w2s + 128;                    // 256
    const int r0 = blockIdx.x * 16, tid = threadIdx.x;

    for (int idx = tid; idx < 16384; idx += 256) buf[idx] = w_out[idx];
    for (int idx = tid; idx < 2048; idx += 256) sy[idx] = g_ysum[r0 * 128 + idx];
    if (tid < 128) w2s[tid] = w2[tid];
    __syncthreads();
    const int rg = tid >> 5, hg = tid & 31;
    float a[2][4];
#pragma unroll
    for (int rr = 0; rr < 2; rr++)
#pragma unroll
        for (int c = 0; c < 4; c++) a[rr][c] = 0.0f;
    for (int k = 0; k < 128; k++) {
        float4 wb = *reinterpret_cast<const float4*>(buf + k * 128 + hg * 4);
        float y0 = sy[(rg * 2) * 128 + k], y1 = sy[(rg * 2 + 1) * 128 + k];
        a[0][0] += y0 * wb.x; a[0][1] += y0 * wb.y; a[0][2] += y0 * wb.z; a[0][3] += y0 * wb.w;
        a[1][0] += y1 * wb.x; a[1][1] += y1 * wb.y; a[1][2] += y1 * wb.z; a[1][3] += y1 * wb.w;
    }
    {
        float4 bb = *reinterpret_cast<const float4*>(b_out + hg * 4);
#pragma unroll
        for (int rr = 0; rr < 2; rr++) {
            int grow = (r0 + rg * 2 + rr) * 128 + hg * 4;
            float4 x0 = *reinterpret_cast<const float4*>(g_x + grow);
            *reinterpret_cast<float4*>(xf + (rg * 2 + rr) * 128 + hg * 4) =
                make_float4(x0.x + a[rr][0] + 3.0f * bb.x, x0.y + a[rr][1] + 3.0f * bb.y,
                            x0.z + a[rr][2] + 3.0f * bb.z, x0.w + a[rr][3] + 3.0f * bb.w);
        }
    }
    __syncthreads();
    for (int idx = tid; idx < 16384; idx += 256) buf[idx] = w1[idx];
    __syncthreads();
#pragma unroll
    for (int rr = 0; rr < 2; rr++)
#pragma unroll
        for (int c = 0; c < 4; c++) a[rr][c] = 0.0f;
    for (int k = 0; k < 128; k++) {
        float4 wb = *reinterpret_cast<const float4*>(buf + k * 128 + hg * 4);
        float y0 = xf[(rg * 2) * 128 + k], y1 = xf[(rg * 2 + 1) * 128 + k];
        a[0][0] += y0 * wb.x; a[0][1] += y0 * wb.y; a[0][2] += y0 * wb.z; a[0][3] += y0 * wb.w;
        a[1][0] += y1 * wb.x; a[1][1] += y1 * wb.y; a[1][2] += y1 * wb.z; a[1][3] += y1 * wb.w;
    }
    __syncthreads();
    {
        float4 bb = *reinterpret_cast<const float4*>(b1 + hg * 4);
#pragma unroll
        for (int rr = 0; rr < 2; rr++)
            *reinterpret_cast<float4*>(sy + (rg * 2 + rr) * 128 + hg * 4) =
                make_float4(sspf(a[rr][0] + bb.x), sspf(a[rr][1] + bb.y),
                            sspf(a[rr][2] + bb.z), sspf(a[rr][3] + bb.w));
    }
    __syncthreads();
    {
        int row = tid >> 4, seg = tid & 15;
        float s = 0.0f;
#pragma unroll
        for (int t = 0; t < 8; t++)
            s += sy[row * 128 + seg * 8 + t] * w2s[seg * 8 + t];
        part[tid] = s;
    }
    __syncthreads();
    if (tid < 16) {
        float s = 0.0f;
#pragma unroll
        for (int q = 0; q < 16; q++) s += part[tid * 16 + q];
        out[r0 + tid] = s + b2[0];
    }
}

extern "C" void kernel_launch(void* const* d_in, const int* in_sizes, int n_in,
                              void* d_out, int out_size)
{
    const int*   z       = (const int*)  d_in[0];
    const float* r       = (const float*)d_in[1];
    const float* emb     = (const float*)d_in[2];
    const float* w_in2f  = (const float*)d_in[3];
    const float* w_f1    = (const float*)d_in[4];
    const float* b_f1    = (const float*)d_in[5];
    const float* w_f2    = (const float*)d_in[6];
    const float* b_f2    = (const float*)d_in[7];
    const float* w_f2out = (const float*)d_in[8];
    const float* b_f2out = (const float*)d_in[9];
    const float* w_out   = (const float*)d_in[10];
    const float* b_out   = (const float*)d_in[11];
    const float* w_aw1   = (const float*)d_in[12];
    const float* b_aw1   = (const float*)d_in[13];
    const float* w_aw2   = (const float*)d_in[14];
    const float* b_aw2   = (const float*)d_in[15];
    float* out = (float*)d_out;

    cudaFuncSetAttribute(k_setup, cudaFuncAttributeMaxDynamicSharedMemorySize, 73728);
    cudaFuncSetAttribute(k_cf,    cudaFuncAttributeMaxDynamicSharedMemorySize, 91648);
    cudaFuncSetAttribute(k_ro,    cudaFuncAttributeMaxDynamicSharedMemorySize, 86016);

    k_table<<<512, 128>>>(w_f1, b_f1, w_f2, b_f2);
    k_pack<<<16384, 256>>>();
    k_setup<<<265, 256, 73728>>>(z, emb, w_in2f, w_out, b_out);
    for (int it = 0; it < 3; it++)
        k_cf<<<dim3(8, 32), 256, 91648>>>(r, w_f2out, b_f2out, it & 1);
    k_ro<<<256, 256, 86016>>>(w_out, b_out, w_aw1, b_aw1, w_aw2, b_aw2, out);
}